// round 13
// baseline (speedup 1.0000x reference)
#include <cuda_runtime.h>
#include <math.h>
#include <stdint.h>

// Problem constants
#define NTOK   65536
#define DIM    256
#define KCODE  1024
#define HW     1024
#define MT     256          // tokens per CTA
#define NC     64           // codes per B chunk
#define CHUNKS 16
#define KS     8            // k-steps of 32 int8
#define MARGIN 3.5e-3f
#define APAD   68           // u32 (int8x4) per A row (64 + 4 pad) -> 272B stride
#define BPAD   68
#define BUFB   (NC*BPAD*4)  // 17408 bytes per B buffer
// quantization: x_int = rn(x * 127/6), c_int = rn(c * 127*1024)
#define XSCALE (127.0f/6.0f)
#define CSCALE 130048.0f
#define SCALE2 (12.0f/16516096.0f)   // 2 * (6/127) * (1/(1024*127))

// smem byte offsets
#define OFF_A     0                             // 256*68*4 = 69632
#define OFF_B     69632                         // 2*17408 = 34816 -> 104448
#define OFF_CN    104448                        // 1024 f32 -> 108544
#define OFF_CANDV 108544                        // 256*16 f32 = 16384 -> 124928
#define OFF_CANDI 124928                        // 256*16 i32 = 16384 -> 141312
#define OFF_SIDX  141312                        // 256 u32 -> 142336
#define OFF_XN    142336                        // 256 f32 -> 143360
#define OFF_RED   143360                        // 256 f32 -> 144384
#define SMEM_TOTAL 144384

__device__ __align__(16) float    g_cnorm[KCODE];
__device__ __align__(16) uint32_t g_cbi8[KCODE * DIM / 4];  // int8 codebook, k-packed u32
__device__ int    g_idx[NTOK];
__device__ int    g_counts[KCODE];
__device__ double g_loss;

// ---------------- helpers ----------------
__device__ __forceinline__ uint32_t smem_u32(const void* p) {
    uint32_t a;
    asm("{ .reg .u64 t; cvta.to.shared.u64 t, %1; cvt.u32.u64 %0, t; }" : "=r"(a) : "l"(p));
    return a;
}
__device__ __forceinline__ int q8(float v, float sc) {
    int r = __float2int_rn(v * sc);
    r = r > 127 ? 127 : (r < -127 ? -127 : r);
    return r & 255;
}
__device__ __forceinline__ void imma_s8(int* c, uint32_t a0, uint32_t a1,
                                        uint32_t a2, uint32_t a3,
                                        uint32_t b0, uint32_t b1) {
    asm volatile("mma.sync.aligned.m16n8k32.row.col.s32.s8.s8.s32 "
                 "{%0,%1,%2,%3}, {%4,%5,%6,%7}, {%8,%9}, {%0,%1,%2,%3};"
                 : "+r"(c[0]), "+r"(c[1]), "+r"(c[2]), "+r"(c[3])
                 : "r"(a0), "r"(a1), "r"(a2), "r"(a3), "r"(b0), "r"(b1));
}
__device__ __forceinline__ void cp_async16(uint32_t dst, const void* src) {
    asm volatile("cp.async.cg.shared.global [%0], [%1], 16;"
                 :: "r"(dst), "l"(__cvta_generic_to_global(src)) : "memory");
}
#define CP_COMMIT() asm volatile("cp.async.commit_group;" ::: "memory")
#define CP_WAIT1()  asm volatile("cp.async.wait_group 1;" ::: "memory")
#define CP_WAIT0()  asm volatile("cp.async.wait_group 0;" ::: "memory")

// Sorted top-4 insertion: keeps the 4 SMALLEST (ascending). Min never evicted.
#define SPUSH(V0,V1,V2,V3,I0,I1,I2,I3, sval, nval)                         \
    do {                                                                   \
        float _s = (sval); int _n = (nval);                                \
        if (_s < V3) {                                                     \
            if (_s < V1) {                                                 \
                V3 = V2; I3 = I2; V2 = V1; I2 = I1;                        \
                if (_s < V0) { V1 = V0; I1 = I0; V0 = _s; I0 = _n; }       \
                else         { V1 = _s; I1 = _n; }                         \
            } else {                                                       \
                if (_s < V2) { V3 = V2; I3 = I2; V2 = _s; I2 = _n; }       \
                else         { V3 = _s; I3 = _n; }                         \
            }                                                              \
        }                                                                  \
    } while (0)

// ---------------------------------------------------------------------------
// Kernel A: sequential fp32 codebook norms (bit-identical to ref reduce) +
// int8 codebook conversion + zero accumulators.
// ---------------------------------------------------------------------------
__global__ void prep_kernel(const float* __restrict__ cb) {
    int gid = blockIdx.x * blockDim.x + threadIdx.x;
    if (gid < KCODE) {
        const float4* row = (const float4*)(cb + (size_t)gid * DIM);
        uint32_t* dst = g_cbi8 + (size_t)gid * (DIM / 4);
        float s = 0.f;
        #pragma unroll 4
        for (int q = 0; q < DIM / 4; q++) {
            float4 v = row[q];
            s = __fadd_rn(s, __fmul_rn(v.x, v.x));
            s = __fadd_rn(s, __fmul_rn(v.y, v.y));
            s = __fadd_rn(s, __fmul_rn(v.z, v.z));
            s = __fadd_rn(s, __fmul_rn(v.w, v.w));
            dst[q] = (uint32_t)q8(v.x, CSCALE) | ((uint32_t)q8(v.y, CSCALE) << 8)
                   | ((uint32_t)q8(v.z, CSCALE) << 16) | ((uint32_t)q8(v.w, CSCALE) << 24);
        }
        g_cnorm[gid] = s;
        g_counts[gid] = 0;
    }
    if (gid == 0) g_loss = 0.0;
}

// ---------------------------------------------------------------------------
// Main fused kernel: int8 mma.sync scoring + sorted top-4 candidate rings +
// exact fp32 rescue + argmin + histogram + loss + fused NCHW gather.
// 256 CTAs x 256 threads, 1 CTA/SM.
// ---------------------------------------------------------------------------
__global__ __launch_bounds__(256, 1)
void argmin_kernel(const float* __restrict__ x, const float* __restrict__ cb,
                   float* __restrict__ out_idx_f, float* __restrict__ out_q) {
    extern __shared__ char smem[];
    uint32_t* Au    = (uint32_t*)(smem + OFF_A);
    uint32_t* Bu0   = (uint32_t*)(smem + OFF_B);
    float*    cnS   = (float*)(smem + OFF_CN);
    float*    candv = (float*)(smem + OFF_CANDV);
    int*      candi = (int*)(smem + OFF_CANDI);
    uint32_t* sidxS = (uint32_t*)(smem + OFF_SIDX);
    float*    xnS   = (float*)(smem + OFF_XN);
    float*    redS  = (float*)(smem + OFF_RED);

    const uint32_t sbB = smem_u32(smem + OFF_B);

    const int tid  = threadIdx.x;
    const int lane = tid & 31;
    const int wid  = tid >> 5;
    const int g    = lane >> 2;
    const int t    = lane & 3;

    const int t0   = blockIdx.x * MT;
    const int b    = t0 >> 10;
    const int tloc = t0 & (HW - 1);
    const float* xb = x + (size_t)b * DIM * HW + tloc;   // (d,m): xb[d*HW+m]
    float* ob = out_q + (size_t)b * DIM * HW + tloc;

    // ---- issue B chunk 0 cp.async (overlaps A pass): 64 rows x 16 x 16B ----
    {
        #pragma unroll
        for (int it = 0; it < 4; it++) {
            int e = tid + 256 * it;               // 0..1023
            int n = e >> 4, seg = e & 15;
            cp_async16(sbB + (uint32_t)(n * (BPAD * 4) + seg * 16),
                       g_cbi8 + (size_t)n * (DIM / 4) + seg * 4);
        }
        CP_COMMIT();
    }

    // ---- codebook norms to smem ----
    ((float4*)cnS)[tid] = ((const float4*)g_cnorm)[tid];

    // ---- A pass: exact sequential xn + int8 A tile (token m = tid) ----
    {
        const float* xp = xb + tid;
        float xn = 0.f;
        uint32_t pk = 0;
        #pragma unroll 8
        for (int d = 0; d < DIM; d++) {
            float v = xp[(size_t)d * HW];
            xn = __fadd_rn(xn, __fmul_rn(v, v));
            pk |= (uint32_t)q8(v, XSCALE) << ((d & 3) * 8);
            if ((d & 3) == 3) { Au[tid * APAD + (d >> 2)] = pk; pk = 0; }
        }
        xnS[tid] = xn;
    }
    __syncthreads();

    // ---- MMA setup: warp covers rows [wid*32, wid*32+32) ----
    const int warpM = wid;
    const int rowbase = warpM * 32 + g;           // rows rowbase + 8*ri
    uint32_t* Ap = Au + (warpM * 32 + g) * APAD + t;

    int acc[2][8][4];
    // 4 sorted top-4 rings (one per row handled by this thread)
    float r0v0=INFINITY,r0v1=INFINITY,r0v2=INFINITY,r0v3=INFINITY;
    float r1v0=INFINITY,r1v1=INFINITY,r1v2=INFINITY,r1v3=INFINITY;
    float r2v0=INFINITY,r2v1=INFINITY,r2v2=INFINITY,r2v3=INFINITY;
    float r3v0=INFINITY,r3v1=INFINITY,r3v2=INFINITY,r3v3=INFINITY;
    int r0i0=0,r0i1=0,r0i2=0,r0i3=0;
    int r1i0=0,r1i1=0,r1i2=0,r1i3=0;
    int r2i0=0,r2i1=0,r2i2=0,r2i3=0;
    int r3i0=0,r3i1=0,r3i2=0,r3i3=0;

    for (int c = 0; c < CHUNKS; c++) {
        // issue chunk c+1 into the other buffer
        if (c + 1 < CHUNKS) {
            const uint32_t base = sbB + (uint32_t)(((c + 1) & 1) * BUFB);
            const uint32_t* srcb = g_cbi8 + (size_t)(c + 1) * NC * (DIM / 4);
            #pragma unroll
            for (int it = 0; it < 4; it++) {
                int e = tid + 256 * it;
                int n = e >> 4, seg = e & 15;
                cp_async16(base + (uint32_t)(n * (BPAD * 4) + seg * 16),
                           srcb + (size_t)n * (DIM / 4) + seg * 4);
            }
        }
        CP_COMMIT();
        if (c + 1 < CHUNKS) CP_WAIT1(); else CP_WAIT0();
        __syncthreads();                          // chunk c visible to all warps

        #pragma unroll
        for (int i = 0; i < 2; i++)
            #pragma unroll
            for (int j = 0; j < 8; j++)
                #pragma unroll
                for (int e = 0; e < 4; e++) acc[i][j][e] = 0;

        uint32_t* Br = Bu0 + (c & 1) * (NC * BPAD) + g * BPAD + t;

        #pragma unroll
        for (int ks = 0; ks < KS; ks++) {
            const int col = ks * 8;               // u32 column (32 int8 per k-step)
            uint32_t a0 = Ap[col],                 a1 = Ap[8 * APAD + col];
            uint32_t a2 = Ap[col + 4],             a3 = Ap[8 * APAD + col + 4];
            uint32_t a4 = Ap[16 * APAD + col],     a5 = Ap[24 * APAD + col];
            uint32_t a6 = Ap[16 * APAD + col + 4], a7 = Ap[24 * APAD + col + 4];
            #pragma unroll
            for (int j = 0; j < 8; j++) {
                uint32_t b0 = Br[j * 8 * BPAD + col];
                uint32_t b1 = Br[j * 8 * BPAD + col + 4];
                imma_s8(acc[0][j], a0, a1, a2, a3, b0, b1);
                imma_s8(acc[1][j], a4, a5, a6, a7, b0, b1);
            }
        }

        // fold chunk scores into sorted rings
        const int cb0 = c * NC;
        #pragma unroll
        for (int j = 0; j < 8; j++) {
            int n0 = cb0 + j * 8 + 2 * t;
            float cn0 = cnS[n0], cn1 = cnS[n0 + 1];
            {
                float s00 = fmaf(-SCALE2, (float)acc[0][j][0], cn0);
                float s01 = fmaf(-SCALE2, (float)acc[0][j][1], cn1);
                float s10 = fmaf(-SCALE2, (float)acc[0][j][2], cn0);
                float s11 = fmaf(-SCALE2, (float)acc[0][j][3], cn1);
                SPUSH(r0v0,r0v1,r0v2,r0v3, r0i0,r0i1,r0i2,r0i3, s00, n0);
                SPUSH(r0v0,r0v1,r0v2,r0v3, r0i0,r0i1,r0i2,r0i3, s01, n0 + 1);
                SPUSH(r1v0,r1v1,r1v2,r1v3, r1i0,r1i1,r1i2,r1i3, s10, n0);
                SPUSH(r1v0,r1v1,r1v2,r1v3, r1i0,r1i1,r1i2,r1i3, s11, n0 + 1);
            }
            {
                float s00 = fmaf(-SCALE2, (float)acc[1][j][0], cn0);
                float s01 = fmaf(-SCALE2, (float)acc[1][j][1], cn1);
                float s10 = fmaf(-SCALE2, (float)acc[1][j][2], cn0);
                float s11 = fmaf(-SCALE2, (float)acc[1][j][3], cn1);
                SPUSH(r2v0,r2v1,r2v2,r2v3, r2i0,r2i1,r2i2,r2i3, s00, n0);
                SPUSH(r2v0,r2v1,r2v2,r2v3, r2i0,r2i1,r2i2,r2i3, s01, n0 + 1);
                SPUSH(r3v0,r3v1,r3v2,r3v3, r3i0,r3i1,r3i2,r3i3, s10, n0);
                SPUSH(r3v0,r3v1,r3v2,r3v3, r3i0,r3i1,r3i2,r3i3, s11, n0 + 1);
            }
        }
        __syncthreads();                          // all reads of buf c&1 done
    }

    // ---- write candidates: fixed slots, race-free (16 per token) ----
    {
        int base0 = rowbase * 16 + t * 4;
        candv[base0 + 0] = r0v0; candi[base0 + 0] = r0i0;
        candv[base0 + 1] = r0v1; candi[base0 + 1] = r0i1;
        candv[base0 + 2] = r0v2; candi[base0 + 2] = r0i2;
        candv[base0 + 3] = r0v3; candi[base0 + 3] = r0i3;
        int base1 = (rowbase + 8) * 16 + t * 4;
        candv[base1 + 0] = r1v0; candi[base1 + 0] = r1i0;
        candv[base1 + 1] = r1v1; candi[base1 + 1] = r1i1;
        candv[base1 + 2] = r1v2; candi[base1 + 2] = r1i2;
        candv[base1 + 3] = r1v3; candi[base1 + 3] = r1i3;
        int base2 = (rowbase + 16) * 16 + t * 4;
        candv[base2 + 0] = r2v0; candi[base2 + 0] = r2i0;
        candv[base2 + 1] = r2v1; candi[base2 + 1] = r2i1;
        candv[base2 + 2] = r2v2; candi[base2 + 2] = r2i2;
        candv[base2 + 3] = r2v3; candi[base2 + 3] = r2i3;
        int base3 = (rowbase + 24) * 16 + t * 4;
        candv[base3 + 0] = r3v0; candi[base3 + 0] = r3i0;
        candv[base3 + 1] = r3v1; candi[base3 + 1] = r3i1;
        candv[base3 + 2] = r3v2; candi[base3 + 2] = r3i2;
        candv[base3 + 3] = r3v3; candi[base3 + 3] = r3i3;
    }
    __syncthreads();

    // ---- final per-token selection + exact rescue (token m = tid) ----
    float tok_loss = 0.f;
    int   bei = 0;
    {
        const int m = tid;
        const float xn = xnS[m];

        // scan 16 candidates: approx min + compact within-margin list
        float vmin = INFINITY; int bimin = 0;
        #pragma unroll
        for (int sl = 0; sl < 16; sl++) {
            float v = candv[m * 16 + sl];
            if (v < vmin) { vmin = v; bimin = candi[m * 16 + sl]; }
        }
        const float thr = vmin + MARGIN;
        int list[16]; int cnt = 0;
        for (int sl = 0; sl < 16; sl++) {
            if (candv[m * 16 + sl] <= thr) list[cnt++] = candi[m * 16 + sl];
        }

        if (cnt == 1) {
            bei = bimin;
            tok_loss = __fadd_rn(xn, vmin);
        } else {
            float bev = __int_as_float(0x7F800000);
            bei = 0x7fffffff;
            for (int base = 0; base < cnt; base += 4) {
                bool val[4]; int nn[4];
                #pragma unroll
                for (int q = 0; q < 4; q++) {
                    int sl = base + q;
                    bool v = (sl < cnt);
                    val[q] = v;
                    nn[q] = v ? list[sl] : list[0];
                }
                const float* p0 = cb + (size_t)nn[0] * DIM;
                const float* p1 = cb + (size_t)nn[1] * DIM;
                const float* p2 = cb + (size_t)nn[2] * DIM;
                const float* p3 = cb + (size_t)nn[3] * DIM;
                float a0 = 0.f, a1 = 0.f, a2 = 0.f, a3 = 0.f;
                #pragma unroll 8
                for (int d = 0; d < DIM; d++) {
                    float a = xb[(size_t)d * HW + m];    // exact f32 x
                    a0 = __fmaf_rn(a, p0[d], a0);
                    a1 = __fmaf_rn(a, p1[d], a1);
                    a2 = __fmaf_rn(a, p2[d], a2);
                    a3 = __fmaf_rn(a, p3[d], a3);
                }
                float accs[4] = {a0, a1, a2, a3};
                #pragma unroll
                for (int q = 0; q < 4; q++) {
                    if (!val[q]) continue;
                    float cn = cnS[nn[q]];
                    float t1 = __fadd_rn(xn, cn);
                    float se = __fadd_rn(t1, __fmul_rn(-2.f, accs[q]));
                    if (se < bev || (se == bev && nn[q] < bei)) { bev = se; bei = nn[q]; }
                }
            }
            tok_loss = bev;
        }

        int gt = t0 + m;
        g_idx[gt] = bei;
        out_idx_f[gt] = (float)bei;
        atomicAdd(&g_counts[bei], 1);
        sidxS[m] = (uint32_t)bei;
    }

    // ---- block loss reduction ----
    redS[tid] = tok_loss;
    __syncthreads();
    #pragma unroll
    for (int s = 128; s > 0; s >>= 1) {
        if (tid < s) redS[tid] += redS[tid + s];
        __syncthreads();
    }
    if (tid == 0) atomicAdd(&g_loss, (double)redS[0]);

    // ---- fused gather: quantized rows -> NCHW, staged via smem (A dead) ----
    {
        float* qs = (float*)(smem + OFF_A);       // [256][33]
        const int myidx = (int)sidxS[tid];
        const float4* src = (const float4*)(cb + (size_t)myidx * DIM);
        for (int d0 = 0; d0 < DIM; d0 += 32) {
            __syncthreads();
            #pragma unroll
            for (int q = 0; q < 8; q++) {
                float4 v = src[(d0 >> 2) + q];
                int dd = q * 4;
                qs[tid * 33 + dd + 0] = v.x; qs[tid * 33 + dd + 1] = v.y;
                qs[tid * 33 + dd + 2] = v.z; qs[tid * 33 + dd + 3] = v.w;
            }
            __syncthreads();
            #pragma unroll
            for (int j = 0; j < 32; j++) {
                // element (d0+j, m=tid); bank = (33*m + j) % 32 = (m+j) % 32
                ob[(size_t)(d0 + j) * HW + tid] = qs[tid * 33 + j];
            }
        }
    }
}

// ---------------------------------------------------------------------------
// Finalize: loss + perplexity
// ---------------------------------------------------------------------------
__global__ void finalize_kernel(float* __restrict__ out_loss,
                                float* __restrict__ out_perp) {
    __shared__ float sred[KCODE];
    int t = threadIdx.x;
    float p = (float)g_counts[t] / (float)NTOK;
    sred[t] = p * logf(p + 1e-10f);
    __syncthreads();
    #pragma unroll
    for (int s = 512; s > 0; s >>= 1) {
        if (t < s) sred[t] += sred[t + s];
        __syncthreads();
    }
    if (t == 0) {
        out_perp[0] = expf(-sred[0]);
        out_loss[0] = (float)(1.25 * g_loss / ((double)NTOK * (double)DIM));
    }
}

// ---------------------------------------------------------------------------
extern "C" void kernel_launch(void* const* d_in, const int* in_sizes, int n_in,
                              void* d_out, int out_size) {
    const float* x  = (const float*)d_in[0];
    const float* cb = (const float*)d_in[1];
    if (n_in >= 2 && in_sizes[0] < in_sizes[1]) {
        const float* t = x; x = cb; cb = t;
    }

    float* out      = (float*)d_out;
    float* out_loss = out;
    float* out_q    = out + 1;
    float* out_perp = out + 1 + (size_t)NTOK * DIM;
    float* out_idx  = out + 2 + (size_t)NTOK * DIM;

    static int attr_done = 0;
    if (!attr_done) {
        cudaFuncSetAttribute(argmin_kernel, cudaFuncAttributeMaxDynamicSharedMemorySize, SMEM_TOTAL);
        attr_done = 1;
    }

    prep_kernel   <<<4, 256>>>(cb);
    argmin_kernel <<<NTOK / MT, 256, SMEM_TOTAL>>>(x, cb, out_idx, out_q);
    finalize_kernel<<<1, KCODE>>>(out_loss, out_perp);
}

// round 14
// speedup vs baseline: 1.8488x; 1.8488x over previous
#include <cuda_runtime.h>
#include <math.h>
#include <stdint.h>

// Problem constants
#define NTOK   65536
#define DIM    256
#define KCODE  1024
#define HW     1024
#define MT     256          // tokens per CTA
#define NC     64           // codes per B chunk
#define CHUNKS 16
#define MARGIN 8.0e-4f
#define APAD   132          // u32 (bf16x2) per A row (128 + 4 pad) -> 528B stride
#define BPAD   132
#define BUFB   (NC*BPAD*4)  // 33792 bytes per B buffer

// smem byte offsets
#define OFF_A     0                             // 256*132*4 = 135168
#define OFF_B     135168                        // 2*33792 = 67584 -> 202752
#define OFF_CN    202752                        // 1024 f32 -> 206848
#define OFF_XN    206848                        // 256 f32 -> 207872
#define SMEM_TOTAL 207872
// Aliased onto dead B region AFTER the MMA loop:
#define OFF_CANDV OFF_B                         // 256*16 f32 = 16384
#define OFF_CANDI (OFF_B + 16384)               // 256*16 i32 = 16384
#define OFF_SIDX  (OFF_B + 32768)               // 256 u32
#define OFF_RED   (OFF_B + 33792)               // 256 f32
// Gather staging aliased onto dead A region: 256*33*4 = 33792 bytes

__device__ __align__(16) float    g_cnorm[KCODE];
__device__ __align__(16) uint32_t g_cbf[KCODE * DIM / 2];   // bf16 codebook
__device__ int    g_idx[NTOK];
__device__ int    g_counts[KCODE];
__device__ double g_loss;

// ---------------- helpers ----------------
__device__ __forceinline__ uint32_t smem_u32(const void* p) {
    uint32_t a;
    asm("{ .reg .u64 t; cvta.to.shared.u64 t, %1; cvt.u32.u64 %0, t; }" : "=r"(a) : "l"(p));
    return a;
}
__device__ __forceinline__ uint32_t packbf(float lo, float hi) {
    uint32_t r;
    asm("cvt.rn.bf16x2.f32 %0, %1, %2;" : "=r"(r) : "f"(hi), "f"(lo));
    return r;
}
__device__ __forceinline__ void mma_bf16(float* c, uint32_t a0, uint32_t a1,
                                         uint32_t a2, uint32_t a3,
                                         uint32_t b0, uint32_t b1) {
    asm volatile("mma.sync.aligned.m16n8k16.row.col.f32.bf16.bf16.f32 "
                 "{%0,%1,%2,%3}, {%4,%5,%6,%7}, {%8,%9}, {%0,%1,%2,%3};"
                 : "+f"(c[0]), "+f"(c[1]), "+f"(c[2]), "+f"(c[3])
                 : "r"(a0), "r"(a1), "r"(a2), "r"(a3), "r"(b0), "r"(b1));
}
__device__ __forceinline__ void cp_async16(uint32_t dst, const void* src) {
    asm volatile("cp.async.cg.shared.global [%0], [%1], 16;"
                 :: "r"(dst), "l"(__cvta_generic_to_global(src)) : "memory");
}
#define CP_COMMIT() asm volatile("cp.async.commit_group;" ::: "memory")
#define CP_WAIT1()  asm volatile("cp.async.wait_group 1;" ::: "memory")
#define CP_WAIT0()  asm volatile("cp.async.wait_group 0;" ::: "memory")

// Sorted top-4 insertion: keeps the 4 SMALLEST (ascending). Min never evicted.
#define SPUSH(V0,V1,V2,V3,I0,I1,I2,I3, sval, nval)                         \
    do {                                                                   \
        float _s = (sval); int _n = (nval);                                \
        if (_s < V3) {                                                     \
            if (_s < V1) {                                                 \
                V3 = V2; I3 = I2; V2 = V1; I2 = I1;                        \
                if (_s < V0) { V1 = V0; I1 = I0; V0 = _s; I0 = _n; }       \
                else         { V1 = _s; I1 = _n; }                         \
            } else {                                                       \
                if (_s < V2) { V3 = V2; I3 = I2; V2 = _s; I2 = _n; }       \
                else         { V3 = _s; I3 = _n; }                         \
            }                                                              \
        }                                                                  \
    } while (0)

// ---------------------------------------------------------------------------
// Kernel A: sequential fp32 codebook norms (bit-identical to ref reduce) +
// bf16 codebook conversion + zero accumulators.
// ---------------------------------------------------------------------------
__global__ void prep_kernel(const float* __restrict__ cb) {
    int gid = blockIdx.x * blockDim.x + threadIdx.x;
    if (gid < KCODE) {
        const float4* row = (const float4*)(cb + (size_t)gid * DIM);
        uint32_t* dst = g_cbf + (size_t)gid * (DIM / 2);
        float s = 0.f;
        #pragma unroll 4
        for (int q = 0; q < DIM / 4; q++) {
            float4 v = row[q];
            s = __fadd_rn(s, __fmul_rn(v.x, v.x));
            s = __fadd_rn(s, __fmul_rn(v.y, v.y));
            s = __fadd_rn(s, __fmul_rn(v.z, v.z));
            s = __fadd_rn(s, __fmul_rn(v.w, v.w));
            dst[2 * q]     = packbf(v.x, v.y);
            dst[2 * q + 1] = packbf(v.z, v.w);
        }
        g_cnorm[gid] = s;
        g_counts[gid] = 0;
    }
    if (gid == 0) g_loss = 0.0;
}

// ---------------------------------------------------------------------------
// Main fused kernel: bf16 mma.sync scoring (R6 loop) + sorted top-4 rings +
// exact fp32 rescue + argmin + histogram + loss + fused NCHW gather.
// 256 CTAs x 256 threads, 1 CTA/SM.
// ---------------------------------------------------------------------------
__global__ __launch_bounds__(256, 1)
void argmin_kernel(const float* __restrict__ x, const float* __restrict__ cb,
                   float* __restrict__ out_idx_f, float* __restrict__ out_q) {
    extern __shared__ char smem[];
    uint32_t* Au    = (uint32_t*)(smem + OFF_A);
    uint32_t* Bu0   = (uint32_t*)(smem + OFF_B);
    float*    cnS   = (float*)(smem + OFF_CN);
    float*    xnS   = (float*)(smem + OFF_XN);
    // aliased (valid only after the MMA loop)
    float*    candv = (float*)(smem + OFF_CANDV);
    int*      candi = (int*)(smem + OFF_CANDI);
    uint32_t* sidxS = (uint32_t*)(smem + OFF_SIDX);
    float*    redS  = (float*)(smem + OFF_RED);

    const uint32_t sbB = smem_u32(smem + OFF_B);

    const int tid  = threadIdx.x;
    const int lane = tid & 31;
    const int wid  = tid >> 5;
    const int g    = lane >> 2;
    const int t    = lane & 3;

    const int t0   = blockIdx.x * MT;
    const int b    = t0 >> 10;
    const int tloc = t0 & (HW - 1);
    const float* xb = x + (size_t)b * DIM * HW + tloc;   // (d,m): xb[d*HW+m]
    float* ob = out_q + (size_t)b * DIM * HW + tloc;

    // ---- issue B chunk 0 cp.async (overlaps A pass): 64 rows x 32 x 16B ----
    {
        #pragma unroll
        for (int it = 0; it < 8; it++) {
            int e = tid + 256 * it;               // 0..2047
            int n = e >> 5, s4 = e & 31;
            cp_async16(sbB + (uint32_t)(n * (BPAD * 4) + s4 * 16),
                       g_cbf + (size_t)n * (DIM / 2) + s4 * 4);
        }
        CP_COMMIT();
    }

    // ---- codebook norms to smem ----
    ((float4*)cnS)[tid] = ((const float4*)g_cnorm)[tid];

    // ---- A pass: exact sequential xn + bf16 A tile (token m = tid) ----
    {
        const float* xp = xb + tid;
        float xn = 0.f, prev = 0.f;
        #pragma unroll 8
        for (int d = 0; d < DIM; d++) {
            float v = xp[(size_t)d * HW];
            xn = __fadd_rn(xn, __fmul_rn(v, v));
            if (d & 1) Au[tid * APAD + (d >> 1)] = packbf(prev, v);
            else prev = v;
        }
        xnS[tid] = xn;
    }
    __syncthreads();

    // ---- MMA setup: warp covers rows [wid*32, wid*32+32) ----
    const int warpM = wid;
    const int rowbase = warpM * 32 + g;           // rows rowbase + 8*ri
    uint32_t* Ap = Au + (warpM * 32 + g) * APAD + t;

    float acc[2][8][4];
    // 4 sorted top-4 rings (one per row handled by this thread)
    float r0v0=INFINITY,r0v1=INFINITY,r0v2=INFINITY,r0v3=INFINITY;
    float r1v0=INFINITY,r1v1=INFINITY,r1v2=INFINITY,r1v3=INFINITY;
    float r2v0=INFINITY,r2v1=INFINITY,r2v2=INFINITY,r2v3=INFINITY;
    float r3v0=INFINITY,r3v1=INFINITY,r3v2=INFINITY,r3v3=INFINITY;
    int r0i0=0,r0i1=0,r0i2=0,r0i3=0;
    int r1i0=0,r1i1=0,r1i2=0,r1i3=0;
    int r2i0=0,r2i1=0,r2i2=0,r2i3=0;
    int r3i0=0,r3i1=0,r3i2=0,r3i3=0;

    for (int c = 0; c < CHUNKS; c++) {
        // issue chunk c+1 into the other buffer
        if (c + 1 < CHUNKS) {
            const uint32_t base = sbB + (uint32_t)(((c + 1) & 1) * BUFB);
            const uint32_t* srcb = g_cbf + (size_t)(c + 1) * NC * (DIM / 2);
            #pragma unroll
            for (int it = 0; it < 8; it++) {
                int e = tid + 256 * it;
                int n = e >> 5, s4 = e & 31;
                cp_async16(base + (uint32_t)(n * (BPAD * 4) + s4 * 16),
                           srcb + (size_t)n * (DIM / 2) + s4 * 4);
            }
        }
        CP_COMMIT();
        if (c + 1 < CHUNKS) CP_WAIT1(); else CP_WAIT0();
        __syncthreads();                          // chunk c visible to all warps

        #pragma unroll
        for (int i = 0; i < 2; i++)
            #pragma unroll
            for (int j = 0; j < 8; j++)
                #pragma unroll
                for (int e = 0; e < 4; e++) acc[i][j][e] = 0.f;

        uint32_t* Br = Bu0 + (c & 1) * (NC * BPAD) + g * BPAD + t;

        #pragma unroll
        for (int ks = 0; ks < 16; ks++) {
            const int col = ks * 8;               // u32 column
            uint32_t a0 = Ap[col],                 a1 = Ap[8 * APAD + col];
            uint32_t a2 = Ap[col + 4],             a3 = Ap[8 * APAD + col + 4];
            uint32_t a4 = Ap[16 * APAD + col],     a5 = Ap[24 * APAD + col];
            uint32_t a6 = Ap[16 * APAD + col + 4], a7 = Ap[24 * APAD + col + 4];
            #pragma unroll
            for (int j = 0; j < 8; j++) {
                uint32_t b0 = Br[j * 8 * BPAD + col];
                uint32_t b1 = Br[j * 8 * BPAD + col + 4];
                mma_bf16(acc[0][j], a0, a1, a2, a3, b0, b1);
                mma_bf16(acc[1][j], a4, a5, a6, a7, b0, b1);
            }
        }

        // fold chunk scores into sorted rings
        const int cb0 = c * NC;
        #pragma unroll
        for (int j = 0; j < 8; j++) {
            int n0 = cb0 + j * 8 + 2 * t;
            float cn0 = cnS[n0], cn1 = cnS[n0 + 1];
            {
                float s00 = fmaf(-2.f, acc[0][j][0], cn0);
                float s01 = fmaf(-2.f, acc[0][j][1], cn1);
                float s10 = fmaf(-2.f, acc[0][j][2], cn0);
                float s11 = fmaf(-2.f, acc[0][j][3], cn1);
                SPUSH(r0v0,r0v1,r0v2,r0v3, r0i0,r0i1,r0i2,r0i3, s00, n0);
                SPUSH(r0v0,r0v1,r0v2,r0v3, r0i0,r0i1,r0i2,r0i3, s01, n0 + 1);
                SPUSH(r1v0,r1v1,r1v2,r1v3, r1i0,r1i1,r1i2,r1i3, s10, n0);
                SPUSH(r1v0,r1v1,r1v2,r1v3, r1i0,r1i1,r1i2,r1i3, s11, n0 + 1);
            }
            {
                float s00 = fmaf(-2.f, acc[1][j][0], cn0);
                float s01 = fmaf(-2.f, acc[1][j][1], cn1);
                float s10 = fmaf(-2.f, acc[1][j][2], cn0);
                float s11 = fmaf(-2.f, acc[1][j][3], cn1);
                SPUSH(r2v0,r2v1,r2v2,r2v3, r2i0,r2i1,r2i2,r2i3, s00, n0);
                SPUSH(r2v0,r2v1,r2v2,r2v3, r2i0,r2i1,r2i2,r2i3, s01, n0 + 1);
                SPUSH(r3v0,r3v1,r3v2,r3v3, r3i0,r3i1,r3i2,r3i3, s10, n0);
                SPUSH(r3v0,r3v1,r3v2,r3v3, r3i0,r3i1,r3i2,r3i3, s11, n0 + 1);
            }
        }
        __syncthreads();                          // all reads of buf c&1 done
    }
    // B region is now dead -> candidate arrays alias it (post-loop barrier done)

    // ---- write candidates: fixed slots, race-free (16 per token) ----
    {
        int base0 = rowbase * 16 + t * 4;
        candv[base0 + 0] = r0v0; candi[base0 + 0] = r0i0;
        candv[base0 + 1] = r0v1; candi[base0 + 1] = r0i1;
        candv[base0 + 2] = r0v2; candi[base0 + 2] = r0i2;
        candv[base0 + 3] = r0v3; candi[base0 + 3] = r0i3;
        int base1 = (rowbase + 8) * 16 + t * 4;
        candv[base1 + 0] = r1v0; candi[base1 + 0] = r1i0;
        candv[base1 + 1] = r1v1; candi[base1 + 1] = r1i1;
        candv[base1 + 2] = r1v2; candi[base1 + 2] = r1i2;
        candv[base1 + 3] = r1v3; candi[base1 + 3] = r1i3;
        int base2 = (rowbase + 16) * 16 + t * 4;
        candv[base2 + 0] = r2v0; candi[base2 + 0] = r2i0;
        candv[base2 + 1] = r2v1; candi[base2 + 1] = r2i1;
        candv[base2 + 2] = r2v2; candi[base2 + 2] = r2i2;
        candv[base2 + 3] = r2v3; candi[base2 + 3] = r2i3;
        int base3 = (rowbase + 24) * 16 + t * 4;
        candv[base3 + 0] = r3v0; candi[base3 + 0] = r3i0;
        candv[base3 + 1] = r3v1; candi[base3 + 1] = r3i1;
        candv[base3 + 2] = r3v2; candi[base3 + 2] = r3i2;
        candv[base3 + 3] = r3v3; candi[base3 + 3] = r3i3;
    }
    __syncthreads();

    // ---- final per-token selection + exact rescue (token m = tid) ----
    float tok_loss = 0.f;
    int   bei = 0;
    {
        const int m = tid;
        const float xn = xnS[m];

        // scan 16 candidates: approx min + compact within-margin list
        float vmin = INFINITY; int bimin = 0;
        #pragma unroll
        for (int sl = 0; sl < 16; sl++) {
            float v = candv[m * 16 + sl];
            if (v < vmin) { vmin = v; bimin = candi[m * 16 + sl]; }
        }
        const float thr = vmin + MARGIN;
        int list[16]; int cnt = 0;
        for (int sl = 0; sl < 16; sl++) {
            if (candv[m * 16 + sl] <= thr) list[cnt++] = candi[m * 16 + sl];
        }

        if (cnt == 1) {
            bei = bimin;
            tok_loss = __fadd_rn(xn, vmin);
        } else {
            float bev = __int_as_float(0x7F800000);
            bei = 0x7fffffff;
            for (int base = 0; base < cnt; base += 4) {
                bool val[4]; int nn[4];
                #pragma unroll
                for (int q = 0; q < 4; q++) {
                    int sl = base + q;
                    bool v = (sl < cnt);
                    val[q] = v;
                    nn[q] = v ? list[sl] : list[0];
                }
                const float* p0 = cb + (size_t)nn[0] * DIM;
                const float* p1 = cb + (size_t)nn[1] * DIM;
                const float* p2 = cb + (size_t)nn[2] * DIM;
                const float* p3 = cb + (size_t)nn[3] * DIM;
                float a0 = 0.f, a1 = 0.f, a2 = 0.f, a3 = 0.f;
                #pragma unroll 8
                for (int d = 0; d < DIM; d++) {
                    float a = xb[(size_t)d * HW + m];    // exact f32 x
                    a0 = __fmaf_rn(a, p0[d], a0);
                    a1 = __fmaf_rn(a, p1[d], a1);
                    a2 = __fmaf_rn(a, p2[d], a2);
                    a3 = __fmaf_rn(a, p3[d], a3);
                }
                float accs[4] = {a0, a1, a2, a3};
                #pragma unroll
                for (int q = 0; q < 4; q++) {
                    if (!val[q]) continue;
                    float cn = cnS[nn[q]];
                    float t1 = __fadd_rn(xn, cn);
                    float se = __fadd_rn(t1, __fmul_rn(-2.f, accs[q]));
                    if (se < bev || (se == bev && nn[q] < bei)) { bev = se; bei = nn[q]; }
                }
            }
            tok_loss = bev;
        }

        int gt = t0 + m;
        g_idx[gt] = bei;
        out_idx_f[gt] = (float)bei;
        atomicAdd(&g_counts[bei], 1);
        sidxS[m] = (uint32_t)bei;
    }

    // ---- block loss reduction ----
    redS[tid] = tok_loss;
    __syncthreads();
    #pragma unroll
    for (int s = 128; s > 0; s >>= 1) {
        if (tid < s) redS[tid] += redS[tid + s];
        __syncthreads();
    }
    if (tid == 0) atomicAdd(&g_loss, (double)redS[0]);

    // ---- fused gather: quantized rows -> NCHW, staged via smem (A dead) ----
    {
        float* qs = (float*)(smem + OFF_A);       // [256][33]
        const int myidx = (int)sidxS[tid];
        const float4* src = (const float4*)(cb + (size_t)myidx * DIM);
        for (int d0 = 0; d0 < DIM; d0 += 32) {
            __syncthreads();
            #pragma unroll
            for (int q = 0; q < 8; q++) {
                float4 v = src[(d0 >> 2) + q];
                int dd = q * 4;
                qs[tid * 33 + dd + 0] = v.x; qs[tid * 33 + dd + 1] = v.y;
                qs[tid * 33 + dd + 2] = v.z; qs[tid * 33 + dd + 3] = v.w;
            }
            __syncthreads();
            #pragma unroll
            for (int j = 0; j < 32; j++) {
                // element (d0+j, m=tid); bank = (33*m + j) % 32 = (m+j) % 32
                ob[(size_t)(d0 + j) * HW + tid] = qs[tid * 33 + j];
            }
        }
    }
}

// ---------------------------------------------------------------------------
// Finalize: loss + perplexity
// ---------------------------------------------------------------------------
__global__ void finalize_kernel(float* __restrict__ out_loss,
                                float* __restrict__ out_perp) {
    __shared__ float sred[KCODE];
    int t = threadIdx.x;
    float p = (float)g_counts[t] / (float)NTOK;
    sred[t] = p * logf(p + 1e-10f);
    __syncthreads();
    #pragma unroll
    for (int s = 512; s > 0; s >>= 1) {
        if (t < s) sred[t] += sred[t + s];
        __syncthreads();
    }
    if (t == 0) {
        out_perp[0] = expf(-sred[0]);
        out_loss[0] = (float)(1.25 * g_loss / ((double)NTOK * (double)DIM));
    }
}

// ---------------------------------------------------------------------------
extern "C" void kernel_launch(void* const* d_in, const int* in_sizes, int n_in,
                              void* d_out, int out_size) {
    const float* x  = (const float*)d_in[0];
    const float* cb = (const float*)d_in[1];
    if (n_in >= 2 && in_sizes[0] < in_sizes[1]) {
        const float* t = x; x = cb; cb = t;
    }

    float* out      = (float*)d_out;
    float* out_loss = out;
    float* out_q    = out + 1;
    float* out_perp = out + 1 + (size_t)NTOK * DIM;
    float* out_idx  = out + 2 + (size_t)NTOK * DIM;

    static int attr_done = 0;
    if (!attr_done) {
        cudaFuncSetAttribute(argmin_kernel, cudaFuncAttributeMaxDynamicSharedMemorySize, SMEM_TOTAL);
        attr_done = 1;
    }

    prep_kernel   <<<4, 256>>>(cb);
    argmin_kernel <<<NTOK / MT, 256, SMEM_TOTAL>>>(x, cb, out_idx, out_q);
    finalize_kernel<<<1, KCODE>>>(out_loss, out_perp);
}

// round 16
// speedup vs baseline: 2.3111x; 1.2500x over previous
#include <cuda_runtime.h>
#include <math.h>
#include <stdint.h>

// Problem constants
#define NTOK   65536
#define DIM    256
#define KCODE  1024
#define HW     1024
#define MT     256          // tokens per CTA
#define NC     64           // codes per B chunk
#define CHUNKS 16
#define MARGIN 8.0e-4f
#define NSLOT  8
#define APAD   132          // u32 (bf16x2) per A row (128 + 4 pad)
#define BPAD   132
#define BUFB   (NC*BPAD*4)  // 33792 bytes per B buffer

// smem byte offsets (identical to the 265us R6 kernel)
#define OFF_A     0                             // 256*132*4 = 135168
#define OFF_B     135168                        // 2*33792 = 67584
#define OFF_CN    202752                        // 1024 f32
#define OFF_CANDV 206848                        // 256*8 f32
#define OFF_CANDI 215040                        // 256*8 i32
#define OFF_THR   223232                        // 256 u32
#define OFF_CNT   224256                        // 256 u32
#define OFF_XN    225280                        // 256 f32
#define OFF_RED   226304                        // 256 f32
#define SMEM_TOTAL 227328

__device__ __align__(16) float    g_cnorm[KCODE];
__device__ __align__(16) uint32_t g_cbf[KCODE * DIM / 2];   // bf16 codebook
__device__ int    g_idx[NTOK];
__device__ int    g_counts[KCODE];
__device__ double g_loss;

// ---------------- helpers ----------------
__device__ __forceinline__ uint32_t smem_u32(const void* p) {
    uint32_t a;
    asm("{ .reg .u64 t; cvta.to.shared.u64 t, %1; cvt.u32.u64 %0, t; }" : "=r"(a) : "l"(p));
    return a;
}
__device__ __forceinline__ uint32_t fkey(float f) {
    uint32_t u = __float_as_uint(f);
    return u ^ (uint32_t)(((int32_t)u >> 31) | 0x80000000);
}
__device__ __forceinline__ float fdec(uint32_t k) {
    uint32_t u = (k & 0x80000000u) ? (k ^ 0x80000000u) : ~k;
    return __uint_as_float(u);
}
__device__ __forceinline__ uint32_t packbf(float lo, float hi) {
    uint32_t r;
    asm("cvt.rn.bf16x2.f32 %0, %1, %2;" : "=r"(r) : "f"(hi), "f"(lo));
    return r;
}
__device__ __forceinline__ void mma_bf16(float* c, uint32_t a0, uint32_t a1,
                                         uint32_t a2, uint32_t a3,
                                         uint32_t b0, uint32_t b1) {
    asm volatile("mma.sync.aligned.m16n8k16.row.col.f32.bf16.bf16.f32 "
                 "{%0,%1,%2,%3}, {%4,%5,%6,%7}, {%8,%9}, {%0,%1,%2,%3};"
                 : "+f"(c[0]), "+f"(c[1]), "+f"(c[2]), "+f"(c[3])
                 : "r"(a0), "r"(a1), "r"(a2), "r"(a3), "r"(b0), "r"(b1));
}
__device__ __forceinline__ void cp_async16(uint32_t dst, const void* src) {
    asm volatile("cp.async.cg.shared.global [%0], [%1], 16;"
                 :: "r"(dst), "l"(__cvta_generic_to_global(src)) : "memory");
}
#define CP_COMMIT() asm volatile("cp.async.commit_group;" ::: "memory")
#define CP_WAIT1()  asm volatile("cp.async.wait_group 1;" ::: "memory")
#define CP_WAIT0()  asm volatile("cp.async.wait_group 0;" ::: "memory")

// ---------------------------------------------------------------------------
// Kernel A: sequential fp32 codebook norms (bit-identical chain order; loads
// batched 16x float4 ahead of the chain for MLP) + bf16 conversion + zeroing.
// ---------------------------------------------------------------------------
__global__ void prep_kernel(const float* __restrict__ cb) {
    int gid = blockIdx.x * blockDim.x + threadIdx.x;
    if (gid < KCODE) {
        const float4* row = (const float4*)(cb + (size_t)gid * DIM);
        uint32_t* dst = g_cbf + (size_t)gid * (DIM / 2);
        float s = 0.f;
        for (int bq = 0; bq < 4; bq++) {
            float4 vb[16];
            #pragma unroll
            for (int q = 0; q < 16; q++) vb[q] = row[bq * 16 + q];
            #pragma unroll
            for (int q = 0; q < 16; q++) {
                float4 v = vb[q];
                s = __fadd_rn(s, __fmul_rn(v.x, v.x));
                s = __fadd_rn(s, __fmul_rn(v.y, v.y));
                s = __fadd_rn(s, __fmul_rn(v.z, v.z));
                s = __fadd_rn(s, __fmul_rn(v.w, v.w));
                int qq = bq * 16 + q;
                dst[2 * qq]     = packbf(v.x, v.y);
                dst[2 * qq + 1] = packbf(v.z, v.w);
            }
        }
        g_cnorm[gid] = s;
        g_counts[gid] = 0;
    }
    if (gid == 0) g_loss = 0.0;
}

// ---------------------------------------------------------------------------
// Main fused kernel (R6 hot loop verbatim): bf16 mma.sync + margin rings +
// exact fp32 rescue + argmin + histogram + loss + register-gather NCHW out.
// 256 CTAs x 256 threads, 1 CTA/SM.
// ---------------------------------------------------------------------------
__global__ __launch_bounds__(256, 1)
void argmin_kernel(const float* __restrict__ x, const float* __restrict__ cb,
                   float* __restrict__ out_idx_f, float* __restrict__ out_q) {
    extern __shared__ char smem[];
    uint32_t* Au    = (uint32_t*)(smem + OFF_A);
    uint32_t* Bu0   = (uint32_t*)(smem + OFF_B);
    float*    cnS   = (float*)(smem + OFF_CN);
    float*    candv = (float*)(smem + OFF_CANDV);
    int*      candi = (int*)(smem + OFF_CANDI);
    uint32_t* thrS  = (uint32_t*)(smem + OFF_THR);
    uint32_t* cntS  = (uint32_t*)(smem + OFF_CNT);
    float*    xnS   = (float*)(smem + OFF_XN);
    float*    redS  = (float*)(smem + OFF_RED);

    const uint32_t sbB = smem_u32(smem + OFF_B);

    const int tid  = threadIdx.x;
    const int lane = tid & 31;
    const int wid  = tid >> 5;
    const int g    = lane >> 2;
    const int t    = lane & 3;

    const int t0   = blockIdx.x * MT;
    const int b    = t0 >> 10;
    const int tloc = t0 & (HW - 1);
    const float* xb = x + (size_t)b * DIM * HW + tloc;   // (d,m): xb[d*HW+m]
    float* ob = out_q + (size_t)b * DIM * HW + tloc;

    // ---- issue B chunk 0 cp.async (overlaps A pass) ----
    {
        #pragma unroll
        for (int it = 0; it < 8; it++) {
            int e = tid + 256 * it;               // 0..2047
            int n = e >> 5, s4 = e & 31;
            cp_async16(sbB + (uint32_t)(n * (BPAD * 4) + s4 * 16),
                       g_cbf + (size_t)n * (DIM / 2) + s4 * 4);
        }
        CP_COMMIT();
    }

    // ---- per-token init ----
    thrS[tid] = 0xFF800000u;    // fkey(+inf)
    cntS[tid] = 0;
    ((float4*)cnS)[tid] = ((const float4*)g_cnorm)[tid];

    // ---- A pass: exact sequential xn + bf16 A tile ----
    {
        const float* xp = xb + tid;               // token m = tid
        float xn = 0.f, prev = 0.f;
        #pragma unroll 8
        for (int d = 0; d < DIM; d++) {
            float v = xp[(size_t)d * HW];
            xn = __fadd_rn(xn, __fmul_rn(v, v));
            if (d & 1) Au[tid * APAD + (d >> 1)] = packbf(prev, v);
            else prev = v;
        }
        xnS[tid] = xn;
    }
    __syncthreads();

    // ---- MMA setup ----
    const int warpM = wid;                        // rows warpM*32 .. +31
    uint32_t* Ap = Au + (warpM * 32 + g) * APAD + t;
    const int rowbase = warpM * 32 + g;           // rows rowbase + 8*ri

    float acc[2][8][4];
    float lmin0 = INFINITY, lmin1 = INFINITY, lmin2 = INFINITY, lmin3 = INFINITY;
    float rv0[4], rv1[4], rv2[4], rv3[4];
    int   ri0[4], ri1[4], ri2[4], ri3[4];
    int   rc0 = 0, rc1 = 0, rc2 = 0, rc3 = 0;

#define RING_PUSH(RV, RI, RC, LM, sval, nval)                      \
    do {                                                           \
        if ((sval) < (LM) + MARGIN) {                              \
            RV[3] = RV[2]; RI[3] = RI[2];                          \
            RV[2] = RV[1]; RI[2] = RI[1];                          \
            RV[1] = RV[0]; RI[1] = RI[0];                          \
            RV[0] = (sval); RI[0] = (nval); RC++;                  \
            if ((sval) < (LM)) (LM) = (sval);                      \
        }                                                          \
    } while (0)

    for (int c = 0; c < CHUNKS; c++) {
        // issue chunk c+1 into the other buffer
        if (c + 1 < CHUNKS) {
            const uint32_t base = sbB + (uint32_t)(((c + 1) & 1) * BUFB);
            const uint32_t* srcb = g_cbf + (size_t)(c + 1) * NC * (DIM / 2);
            #pragma unroll
            for (int it = 0; it < 8; it++) {
                int e = tid + 256 * it;
                int n = e >> 5, s4 = e & 31;
                cp_async16(base + (uint32_t)(n * (BPAD * 4) + s4 * 16),
                           srcb + (size_t)n * (DIM / 2) + s4 * 4);
            }
        }
        CP_COMMIT();
        if (c + 1 < CHUNKS) CP_WAIT1(); else CP_WAIT0();
        __syncthreads();                          // chunk c visible to all warps

        #pragma unroll
        for (int i = 0; i < 2; i++)
            #pragma unroll
            for (int j = 0; j < 8; j++)
                #pragma unroll
                for (int e = 0; e < 4; e++) acc[i][j][e] = 0.f;

        uint32_t* Br = Bu0 + (c & 1) * (NC * BPAD) + g * BPAD + t;

        #pragma unroll
        for (int ks = 0; ks < 16; ks++) {
            const int col = ks * 8;               // u32 column
            uint32_t a0 = Ap[col],                 a1 = Ap[8 * APAD + col];
            uint32_t a2 = Ap[col + 4],             a3 = Ap[8 * APAD + col + 4];
            uint32_t a4 = Ap[16 * APAD + col],     a5 = Ap[24 * APAD + col];
            uint32_t a6 = Ap[16 * APAD + col + 4], a7 = Ap[24 * APAD + col + 4];
            #pragma unroll
            for (int j = 0; j < 8; j++) {
                uint32_t b0 = Br[j * 8 * BPAD + col];
                uint32_t b1 = Br[j * 8 * BPAD + col + 4];
                mma_bf16(acc[0][j], a0, a1, a2, a3, b0, b1);
                mma_bf16(acc[1][j], a4, a5, a6, a7, b0, b1);
            }
        }

        // fold chunk scores into register rings
        const int cb0 = c * NC;
        #pragma unroll
        for (int j = 0; j < 8; j++) {
            int n0 = cb0 + j * 8 + 2 * t;
            float cn0 = cnS[n0], cn1 = cnS[n0 + 1];
            {
                float s00 = fmaf(-2.f, acc[0][j][0], cn0);
                float s01 = fmaf(-2.f, acc[0][j][1], cn1);
                float s10 = fmaf(-2.f, acc[0][j][2], cn0);
                float s11 = fmaf(-2.f, acc[0][j][3], cn1);
                RING_PUSH(rv0, ri0, rc0, lmin0, s00, n0);
                RING_PUSH(rv0, ri0, rc0, lmin0, s01, n0 + 1);
                RING_PUSH(rv1, ri1, rc1, lmin1, s10, n0);
                RING_PUSH(rv1, ri1, rc1, lmin1, s11, n0 + 1);
            }
            {
                float s00 = fmaf(-2.f, acc[1][j][0], cn0);
                float s01 = fmaf(-2.f, acc[1][j][1], cn1);
                float s10 = fmaf(-2.f, acc[1][j][2], cn0);
                float s11 = fmaf(-2.f, acc[1][j][3], cn1);
                RING_PUSH(rv2, ri2, rc2, lmin2, s00, n0);
                RING_PUSH(rv2, ri2, rc2, lmin2, s01, n0 + 1);
                RING_PUSH(rv3, ri3, rc3, lmin3, s10, n0);
                RING_PUSH(rv3, ri3, rc3, lmin3, s11, n0 + 1);
            }
        }
        __syncthreads();                          // all reads of buf c&1 done
    }

    // ---- merge: global per-row threshold ----
    atomicMin(&thrS[rowbase],      fkey(lmin0));
    atomicMin(&thrS[rowbase + 8],  fkey(lmin1));
    atomicMin(&thrS[rowbase + 16], fkey(lmin2));
    atomicMin(&thrS[rowbase + 24], fkey(lmin3));
    __syncthreads();

    // ---- filter-write candidates within gmin+MARGIN to shared ----
#define FILTER_ROW(RV, RI, RC, ROW)                                          \
    do {                                                                     \
        float thr = fdec(thrS[ROW]) + MARGIN;                                \
        int k = (RC < 4) ? RC : 4;                                           \
        _Pragma("unroll")                                                    \
        for (int sl = 0; sl < 4; sl++) {                                     \
            if (sl < k && RV[sl] <= thr) {                                   \
                uint32_t old = atomicAdd(&cntS[ROW], 1u);                    \
                if (old < NSLOT) {                                           \
                    candv[(ROW) * NSLOT + old] = RV[sl];                     \
                    candi[(ROW) * NSLOT + old] = RI[sl];                     \
                }                                                            \
            }                                                                \
        }                                                                    \
    } while (0)
    FILTER_ROW(rv0, ri0, rc0, rowbase);
    FILTER_ROW(rv1, ri1, rc1, rowbase + 8);
    FILTER_ROW(rv2, ri2, rc2, rowbase + 16);
    FILTER_ROW(rv3, ri3, rc3, rowbase + 24);
    __syncthreads();

    // ---- final per-token selection + exact rescue (token m = tid) ----
    float tok_loss = 0.f;
    int   bei = 0;
    {
        const int m = tid;
        const float xn = xnS[m];
        uint32_t nv = cntS[m]; if (nv > NSLOT) nv = NSLOT;

        if (nv == 1) {
            bei = candi[m * NSLOT];
            tok_loss = __fadd_rn(xn, candv[m * NSLOT]);
        } else if (nv >= 2) {
            float bev = __int_as_float(0x7F800000);
            bei = 0x7fffffff;
            for (int base = 0; base < NSLOT; base += 4) {
                if (base >= (int)nv) break;
                bool val[4]; int nn[4];
                #pragma unroll
                for (int q = 0; q < 4; q++) {
                    int sl = base + q;
                    bool v = (sl < (int)nv);
                    val[q] = v;
                    nn[q] = v ? candi[m * NSLOT + sl] : 0;
                }
                const float* p0 = cb + (size_t)nn[0] * DIM;
                const float* p1 = cb + (size_t)nn[1] * DIM;
                const float* p2 = cb + (size_t)nn[2] * DIM;
                const float* p3 = cb + (size_t)nn[3] * DIM;
                float a0 = 0.f, a1 = 0.f, a2 = 0.f, a3 = 0.f;
                #pragma unroll 8
                for (int d = 0; d < DIM; d++) {
                    float a = xb[(size_t)d * HW + m];    // exact f32 x
                    a0 = __fmaf_rn(a, p0[d], a0);
                    a1 = __fmaf_rn(a, p1[d], a1);
                    a2 = __fmaf_rn(a, p2[d], a2);
                    a3 = __fmaf_rn(a, p3[d], a3);
                }
                float accs[4] = {a0, a1, a2, a3};
                #pragma unroll
                for (int q = 0; q < 4; q++) {
                    if (!val[q]) continue;
                    float cn = cnS[nn[q]];
                    float t1 = __fadd_rn(xn, cn);
                    float se = __fadd_rn(t1, __fmul_rn(-2.f, accs[q]));
                    if (se < bev || (se == bev && nn[q] < bei)) { bev = se; bei = nn[q]; }
                }
            }
            tok_loss = bev;
        }
        // nv == 0 impossible (the global-min achiever always survives)

        int gt = t0 + m;
        g_idx[gt] = bei;
        out_idx_f[gt] = (float)bei;
        atomicAdd(&g_counts[bei], 1);
    }

    // ---- block loss reduction ----
    redS[tid] = tok_loss;
    __syncthreads();
    #pragma unroll
    for (int s = 128; s > 0; s >>= 1) {
        if (tid < s) redS[tid] += redS[tid + s];
        __syncthreads();
    }
    if (tid == 0) atomicAdd(&g_loss, (double)redS[0]);

    // ---- fused gather: each thread emits its own token's row, register-only.
    // Loads: 16x float4 per 64-d block (L2-hot codebook row gather).
    // Stores: ob[(d0+j)*HW + tid] coalesced across threads for each j.
    {
        const float4* src = (const float4*)(cb + (size_t)bei * DIM);
        #pragma unroll
        for (int d0 = 0; d0 < DIM; d0 += 64) {
            float4 v[16];
            #pragma unroll
            for (int q = 0; q < 16; q++) v[q] = src[(d0 >> 2) + q];
            const float* vf = (const float*)v;
            #pragma unroll
            for (int j = 0; j < 64; j++) {
                ob[(size_t)(d0 + j) * HW + tid] = vf[j];
            }
        }
    }
}

// ---------------------------------------------------------------------------
// Finalize: loss + perplexity
// ---------------------------------------------------------------------------
__global__ void finalize_kernel(float* __restrict__ out_loss,
                                float* __restrict__ out_perp) {
    __shared__ float sred[KCODE];
    int t = threadIdx.x;
    float p = (float)g_counts[t] / (float)NTOK;
    sred[t] = p * logf(p + 1e-10f);
    __syncthreads();
    #pragma unroll
    for (int s = 512; s > 0; s >>= 1) {
        if (t < s) sred[t] += sred[t + s];
        __syncthreads();
    }
    if (t == 0) {
        out_perp[0] = expf(-sred[0]);
        out_loss[0] = (float)(1.25 * g_loss / ((double)NTOK * (double)DIM));
    }
}

// ---------------------------------------------------------------------------
extern "C" void kernel_launch(void* const* d_in, const int* in_sizes, int n_in,
                              void* d_out, int out_size) {
    const float* x  = (const float*)d_in[0];
    const float* cb = (const float*)d_in[1];
    if (n_in >= 2 && in_sizes[0] < in_sizes[1]) {
        const float* t = x; x = cb; cb = t;
    }

    float* out      = (float*)d_out;
    float* out_loss = out;
    float* out_q    = out + 1;
    float* out_perp = out + 1 + (size_t)NTOK * DIM;
    float* out_idx  = out + 2 + (size_t)NTOK * DIM;

    static int attr_done = 0;
    if (!attr_done) {
        cudaFuncSetAttribute(argmin_kernel, cudaFuncAttributeMaxDynamicSharedMemorySize, SMEM_TOTAL);
        attr_done = 1;
    }

    prep_kernel   <<<4, 256>>>(cb);
    argmin_kernel <<<NTOK / MT, 256, SMEM_TOTAL>>>(x, cb, out_idx, out_q);
    finalize_kernel<<<1, KCODE>>>(out_loss, out_perp);
}